// round 1
// baseline (speedup 1.0000x reference)
#include <cuda_runtime.h>

// ---------------------------------------------------------------------------
// SubdivideMeshes: batched GCN (3 layers) + edge-midpoint subdivision.
// B=16, V=100000, E=300000, Fsub=800000, H=16.
// Output layout (float32): [B, V+E, 3] new_verts  then  [B, Fsub, 3] faces.
// ---------------------------------------------------------------------------

constexpr int   B_    = 16;
constexpr int   V_    = 100000;
constexpr int   E_    = 300000;
constexpr int   FSUB  = 800000;
constexpr int   NTOT  = B_ * V_;          // 1,600,000 nodes
constexpr int   ROWS  = V_ + E_;          // 400,000 rows per batch in new_verts
constexpr int   VOUT  = B_ * ROWS * 3;    // 19,200,000 floats (verts region)
constexpr float NEG   = 0.01f;

constexpr int SCAN_B = 1024;
constexpr int NBLK   = (V_ + SCAN_B - 1) / SCAN_B;  // 98

// Scratch (device globals: allocation-free per harness rules)
__device__ float4 g_tA[NTOT * 4];   // 102.4 MB : tt features (16 floats / node)
__device__ float4 g_tB[NTOT * 4];   // 102.4 MB
__device__ int    g_deg[V_];
__device__ int    g_off[V_ + 1];
__device__ int    g_cur[V_];
__device__ int    g_part[256];
__device__ int    g_csr[E_];
__device__ float  g_dinv[V_];

// ---------------- CSR build ----------------

__global__ void k_zero() {
    int i = blockIdx.x * blockDim.x + threadIdx.x;
    if (i < V_) g_deg[i] = 0;
}

__global__ void k_hist(const int* __restrict__ edges) {
    int e = blockIdx.x * blockDim.x + threadIdx.x;
    if (e < E_) atomicAdd(&g_deg[edges[2 * e + 1]], 1);
}

__global__ void k_scan1() {
    __shared__ int sh[SCAN_B];
    int i = blockIdx.x * SCAN_B + threadIdx.x;
    int c = (i < V_) ? g_deg[i] : 0;
    if (i < V_) g_dinv[i] = rsqrtf((float)(c + 1));  // +1 self loop
    sh[threadIdx.x] = c;
    __syncthreads();
    for (int o = 1; o < SCAN_B; o <<= 1) {
        int t = (threadIdx.x >= o) ? sh[threadIdx.x - o] : 0;
        __syncthreads();
        sh[threadIdx.x] += t;
        __syncthreads();
    }
    if (i < V_) g_off[i] = sh[threadIdx.x] - c;  // exclusive within block
    if (threadIdx.x == SCAN_B - 1) g_part[blockIdx.x] = sh[threadIdx.x];
}

__global__ void k_scan2() {
    __shared__ int sh[128];
    int t = threadIdx.x;
    int v = (t < NBLK) ? g_part[t] : 0;
    sh[t] = v;
    __syncthreads();
    for (int o = 1; o < 128; o <<= 1) {
        int x = (t >= o) ? sh[t - o] : 0;
        __syncthreads();
        sh[t] += x;
        __syncthreads();
    }
    if (t < NBLK) g_part[t] = sh[t] - v;  // exclusive
}

__global__ void k_scan3() {
    int i = blockIdx.x * blockDim.x + threadIdx.x;
    if (i < V_) {
        int o = g_off[i] + g_part[i / SCAN_B];
        g_off[i] = o;
        g_cur[i] = o;
    }
    if (i == 0) g_off[V_] = E_;
}

__global__ void k_fill(const int* __restrict__ edges) {
    int e = blockIdx.x * blockDim.x + threadIdx.x;
    if (e < E_) {
        int s = edges[2 * e];
        int d = edges[2 * e + 1];
        int p = atomicAdd(&g_cur[d], 1);
        g_csr[p] = s;
    }
}

// ---------------- Layer 1: tt1 = (x @ W1) * dinv ----------------

__global__ void k_l1(const float* __restrict__ verts, const float* __restrict__ W1) {
    __shared__ float sW[48];
    if (threadIdx.x < 48) sW[threadIdx.x] = W1[threadIdx.x];
    __syncthreads();
    int n = blockIdx.x * blockDim.x + threadIdx.x;
    if (n >= NTOT) return;
    int v = n % V_;
    float x0 = verts[3 * n], x1 = verts[3 * n + 1], x2 = verts[3 * n + 2];
    float dv = g_dinv[v];
    float o[16];
#pragma unroll
    for (int j = 0; j < 16; j++)
        o[j] = (x0 * sW[j] + x1 * sW[16 + j] + x2 * sW[32 + j]) * dv;
    float4* dst = &g_tA[n * 4];
    dst[0] = make_float4(o[0],  o[1],  o[2],  o[3]);
    dst[1] = make_float4(o[4],  o[5],  o[6],  o[7]);
    dst[2] = make_float4(o[8],  o[9],  o[10], o[11]);
    dst[3] = make_float4(o[12], o[13], o[14], o[15]);
}

// --------- Fused AGG(prev layer) + GEMM(next layer), 16 -> 16 ----------
// tout[n] = ( leaky( bias + dv * (tt[n] + sum_nbr tt[s]) ) @ W ) * dv

__global__ void k_agg_gemm16(const float4* __restrict__ tin, float4* __restrict__ tout,
                             const float* __restrict__ W, const float* __restrict__ bias) {
    __shared__ float sW[256];
    __shared__ float sB[16];
    int t = threadIdx.x;
    if (t < 256) sW[t] = W[t];
    if (t < 16)  sB[t] = bias[t];
    __syncthreads();
    int n = blockIdx.x * blockDim.x + t;
    if (n >= NTOT) return;
    int b = n / V_, v = n - b * V_;
    float dv = g_dinv[v];
    int base = b * V_;
    float4 a0 = tin[n * 4], a1 = tin[n * 4 + 1], a2 = tin[n * 4 + 2], a3 = tin[n * 4 + 3];
    int e1 = g_off[v + 1];
    for (int e = g_off[v]; e < e1; e++) {
        int s = (base + g_csr[e]) * 4;
        float4 r0 = tin[s], r1 = tin[s + 1], r2 = tin[s + 2], r3 = tin[s + 3];
        a0.x += r0.x; a0.y += r0.y; a0.z += r0.z; a0.w += r0.w;
        a1.x += r1.x; a1.y += r1.y; a1.z += r1.z; a1.w += r1.w;
        a2.x += r2.x; a2.y += r2.y; a2.z += r2.z; a2.w += r2.w;
        a3.x += r3.x; a3.y += r3.y; a3.z += r3.z; a3.w += r3.w;
    }
    float h[16] = {a0.x, a0.y, a0.z, a0.w, a1.x, a1.y, a1.z, a1.w,
                   a2.x, a2.y, a2.z, a2.w, a3.x, a3.y, a3.z, a3.w};
#pragma unroll
    for (int k = 0; k < 16; k++) {
        float x = sB[k] + dv * h[k];
        h[k] = (x > 0.f) ? x : NEG * x;
    }
    float o[16];
#pragma unroll
    for (int j = 0; j < 16; j++) o[j] = 0.f;
#pragma unroll
    for (int k = 0; k < 16; k++) {
        float lk = h[k];
#pragma unroll
        for (int j = 0; j < 16; j++) o[j] += lk * sW[k * 16 + j];
    }
    float4* dst = &tout[n * 4];
    dst[0] = make_float4(o[0] * dv,  o[1] * dv,  o[2] * dv,  o[3] * dv);
    dst[1] = make_float4(o[4] * dv,  o[5] * dv,  o[6] * dv,  o[7] * dv);
    dst[2] = make_float4(o[8] * dv,  o[9] * dv,  o[10] * dv, o[11] * dv);
    dst[3] = make_float4(o[12] * dv, o[13] * dv, o[14] * dv, o[15] * dv);
}

// --------- Fused AGG(layer2) + GEMM3 (16 -> 3), tt3 into g_tA[n] ----------

__global__ void k_agg_gemm3(const float* __restrict__ W3, const float* __restrict__ b2) {
    __shared__ float sW[48];
    __shared__ float sB[16];
    int t = threadIdx.x;
    if (t < 48) sW[t] = W3[t];
    if (t < 16) sB[t] = b2[t];
    __syncthreads();
    int n = blockIdx.x * blockDim.x + t;
    if (n >= NTOT) return;
    int b = n / V_, v = n - b * V_;
    float dv = g_dinv[v];
    int base = b * V_;
    const float4* __restrict__ tin = g_tB;
    float4 a0 = tin[n * 4], a1 = tin[n * 4 + 1], a2 = tin[n * 4 + 2], a3 = tin[n * 4 + 3];
    int e1 = g_off[v + 1];
    for (int e = g_off[v]; e < e1; e++) {
        int s = (base + g_csr[e]) * 4;
        float4 r0 = tin[s], r1 = tin[s + 1], r2 = tin[s + 2], r3 = tin[s + 3];
        a0.x += r0.x; a0.y += r0.y; a0.z += r0.z; a0.w += r0.w;
        a1.x += r1.x; a1.y += r1.y; a1.z += r1.z; a1.w += r1.w;
        a2.x += r2.x; a2.y += r2.y; a2.z += r2.z; a2.w += r2.w;
        a3.x += r3.x; a3.y += r3.y; a3.z += r3.z; a3.w += r3.w;
    }
    float h[16] = {a0.x, a0.y, a0.z, a0.w, a1.x, a1.y, a1.z, a1.w,
                   a2.x, a2.y, a2.z, a2.w, a3.x, a3.y, a3.z, a3.w};
#pragma unroll
    for (int k = 0; k < 16; k++) {
        float x = sB[k] + dv * h[k];
        h[k] = (x > 0.f) ? x : NEG * x;
    }
    float o0 = 0.f, o1 = 0.f, o2 = 0.f;
#pragma unroll
    for (int k = 0; k < 16; k++) {
        o0 += h[k] * sW[k * 3 + 0];
        o1 += h[k] * sW[k * 3 + 1];
        o2 += h[k] * sW[k * 3 + 2];
    }
    g_tA[n] = make_float4(o0 * dv, o1 * dv, o2 * dv, 0.f);
}

// --------- Final AGG(layer3) + residual, write verts region of d_out ----------

__global__ void k_final(const float* __restrict__ verts, const float* __restrict__ b3,
                        float* __restrict__ out) {
    int n = blockIdx.x * blockDim.x + threadIdx.x;
    if (n >= NTOT) return;
    int b = n / V_, v = n - b * V_;
    float dv = g_dinv[v];
    int base = b * V_;
    float4 a = g_tA[n];
    int e1 = g_off[v + 1];
    for (int e = g_off[v]; e < e1; e++) {
        float4 r = g_tA[base + g_csr[e]];
        a.x += r.x; a.y += r.y; a.z += r.z;
    }
    float r0 = verts[3 * n + 0] + b3[0] + dv * a.x;
    float r1 = verts[3 * n + 1] + b3[1] + dv * a.y;
    float r2 = verts[3 * n + 2] + b3[2] + dv * a.z;
    int o = (b * ROWS + v) * 3;
    out[o + 0] = r0;
    out[o + 1] = r1;
    out[o + 2] = r2;
}

// --------- Edge midpoints ----------

__global__ void k_mid(const int* __restrict__ edges, float* __restrict__ out) {
    int idx = blockIdx.x * blockDim.x + threadIdx.x;
    if (idx >= B_ * E_) return;
    int b = idx / E_, e = idx - b * E_;
    int v0 = edges[2 * e], v1 = edges[2 * e + 1];
    const float* vb = out + (size_t)b * ROWS * 3;
    float mx = 0.5f * (vb[v0 * 3 + 0] + vb[v1 * 3 + 0]);
    float my = 0.5f * (vb[v0 * 3 + 1] + vb[v1 * 3 + 1]);
    float mz = 0.5f * (vb[v0 * 3 + 2] + vb[v1 * 3 + 2]);
    float* mo = out + ((size_t)b * ROWS + V_ + e) * 3;
    mo[0] = mx; mo[1] = my; mo[2] = mz;
}

// --------- Faces broadcast ----------

__global__ void k_faces(const int* __restrict__ faces, float* __restrict__ out) {
    int idx = blockIdx.x * blockDim.x + threadIdx.x;
    if (idx >= B_ * FSUB * 3) return;
    int i = idx % (FSUB * 3);
    out[VOUT + idx] = (float)faces[i];
}

// ---------------------------------------------------------------------------

extern "C" void kernel_launch(void* const* d_in, const int* in_sizes, int n_in,
                              void* d_out, int out_size) {
    const float* verts = (const float*)d_in[0];
    const int*   edges = (const int*)d_in[1];
    const int*   faces = (const int*)d_in[2];
    const float* W1 = (const float*)d_in[3];
    const float* b1 = (const float*)d_in[4];
    const float* W2 = (const float*)d_in[5];
    const float* b2 = (const float*)d_in[6];
    const float* W3 = (const float*)d_in[7];
    const float* b3 = (const float*)d_in[8];
    float* out = (float*)d_out;

    // CSR + dinv build (edge structure identical across batches)
    k_zero <<<(V_ + 255) / 256, 256>>>();
    k_hist <<<(E_ + 255) / 256, 256>>>(edges);
    k_scan1<<<NBLK, SCAN_B>>>();
    k_scan2<<<1, 128>>>();
    k_scan3<<<(V_ + 255) / 256, 256>>>();
    k_fill <<<(E_ + 255) / 256, 256>>>(edges);

    // Faces (independent of GCN path)
    k_faces<<<(B_ * FSUB * 3 + 255) / 256, 256>>>(faces, out);

    // GCN pipeline
    int nb = (NTOT + 255) / 256;
    k_l1<<<nb, 256>>>(verts, W1);
    k_agg_gemm16<<<nb, 256>>>(g_tA, g_tB, W2, b1);   // AGG1 + GEMM2
    k_agg_gemm3 <<<nb, 256>>>(W3, b2);               // AGG2 + GEMM3
    k_final     <<<nb, 256>>>(verts, b3, out);       // AGG3 + residual

    // Midpoints (reads verts region of out written by k_final)
    k_mid<<<(B_ * E_ + 255) / 256, 256>>>(edges, out);
}

// round 2
// speedup vs baseline: 1.2200x; 1.2200x over previous
#include <cuda_runtime.h>

// ---------------------------------------------------------------------------
// SubdivideMeshes: batched GCN (3 layers) + edge-midpoint subdivision.
// B=16, V=100000, E=300000, Fsub=800000, H=16.
// Feature layout transposed to [V][B][H] so one 1KB-contiguous gather per
// (vertex, edge) serves all 16 batches.
// Output (float32): [B, V+E, 3] new_verts then [B, Fsub, 3] faces.
// ---------------------------------------------------------------------------

constexpr int   B_    = 16;
constexpr int   V_    = 100000;
constexpr int   E_    = 300000;
constexpr int   FSUB  = 800000;
constexpr int   ROWS  = V_ + E_;          // 400,000 rows per batch
constexpr int   VOUT  = B_ * ROWS * 3;    // 19,200,000 floats (verts region)
constexpr float NEG   = 0.01f;

constexpr int SCAN_B = 1024;
constexpr int NBLK   = (V_ + SCAN_B - 1) / SCAN_B;  // 98

// Scratch (device globals; allocation-free per harness rules)
__device__ float4 g_tA[V_ * 64];   // [v][b][h] : v*64 + b*4 + h/4   (102.4 MB)
__device__ float4 g_tB[V_ * 64];   // 102.4 MB
__device__ float4 g_tC[V_ * 16];   // [v][b] xyz (tt3)
__device__ float4 g_tD[V_ * 16];   // [v][b] final vertex positions
__device__ int    g_deg[V_];       // static zero-init; re-zeroed by k_fill
__device__ int    g_off[V_ + 1];
__device__ int    g_cur[V_];
__device__ int    g_part[128];
__device__ int    g_csr[E_];
__device__ float  g_dinv[V_];

// ---------------- CSR build ----------------

__global__ void k_hist(const int* __restrict__ edges) {
    int e = blockIdx.x * blockDim.x + threadIdx.x;
    if (e < E_) atomicAdd(&g_deg[edges[2 * e + 1]], 1);
}

__global__ void k_scan1() {
    __shared__ int sh[SCAN_B];
    int i = blockIdx.x * SCAN_B + threadIdx.x;
    int c = (i < V_) ? g_deg[i] : 0;
    if (i < V_) g_dinv[i] = rsqrtf((float)(c + 1));  // +1 self loop
    sh[threadIdx.x] = c;
    __syncthreads();
    for (int o = 1; o < SCAN_B; o <<= 1) {
        int t = (threadIdx.x >= o) ? sh[threadIdx.x - o] : 0;
        __syncthreads();
        sh[threadIdx.x] += t;
        __syncthreads();
    }
    if (i < V_) g_off[i] = sh[threadIdx.x] - c;  // exclusive within block
    if (threadIdx.x == SCAN_B - 1) g_part[blockIdx.x] = sh[threadIdx.x];
}

// Fused: every block redundantly scans the 98 partials, then applies.
__global__ void k_scan2() {
    __shared__ int sh[128];
    int t = threadIdx.x;
    if (t < 128) {
        int v = (t < NBLK) ? g_part[t] : 0;
        sh[t] = v;
    }
    __syncthreads();
    for (int o = 1; o < 128; o <<= 1) {
        int x = (t < 128 && t >= o) ? sh[t - o] : 0;
        __syncthreads();
        if (t < 128) sh[t] += x;
        __syncthreads();
    }
    int i = blockIdx.x * blockDim.x + t;
    if (i < V_) {
        int blk = i / SCAN_B;
        int excl = (blk == 0) ? 0 : sh[blk - 1];
        int o = g_off[i] + excl;
        g_off[i] = o;
        g_cur[i] = o;
    }
    if (i == 0) g_off[V_] = E_;
}

__global__ void k_fill(const int* __restrict__ edges) {
    int e = blockIdx.x * blockDim.x + threadIdx.x;
    if (e < E_) {
        int s = edges[2 * e];
        int d = edges[2 * e + 1];
        int p = atomicAdd(&g_cur[d], 1);
        g_csr[p] = s;
        g_deg[d] = 0;  // reset for the next graph replay (idempotent)
    }
}

// ---------------- Layer 1: tt1[v][b][:] = (x @ W1) * dinv[v] ----------------
// Warp handles 2 vertices; lane l -> (v = 2w + (l>>4), b = l&15).

__global__ void k_l1(const float* __restrict__ verts, const float* __restrict__ W1) {
    __shared__ float sW[48];
    if (threadIdx.x < 48) sW[threadIdx.x] = W1[threadIdx.x];
    __syncthreads();
    int warp = (blockIdx.x * blockDim.x + threadIdx.x) >> 5;
    int lane = threadIdx.x & 31;
    int v = 2 * warp + (lane >> 4);
    if (v >= V_) return;
    int b = lane & 15;
    float dv = g_dinv[v];
    const float* xp = verts + ((size_t)b * V_ + v) * 3;
    float x0 = xp[0], x1 = xp[1], x2 = xp[2];
    float o[16];
#pragma unroll
    for (int j = 0; j < 16; j++)
        o[j] = (x0 * sW[j] + x1 * sW[16 + j] + x2 * sW[32 + j]) * dv;
    float4* dst = &g_tA[(size_t)v * 64 + b * 4];
    dst[0] = make_float4(o[0],  o[1],  o[2],  o[3]);
    dst[1] = make_float4(o[4],  o[5],  o[6],  o[7]);
    dst[2] = make_float4(o[8],  o[9],  o[10], o[11]);
    dst[3] = make_float4(o[12], o[13], o[14], o[15]);
}

// ---- Fused AGG + GEMM (16->16): tout = (leaky(b + dv*(tt[v]+sum tt[s])) @ W) * dv

__global__ void k_agg_gemm16(const float4* __restrict__ tin, float4* __restrict__ tout,
                             const float* __restrict__ W, const float* __restrict__ bias) {
    __shared__ float sW[256];
    __shared__ float sB[16];
    int t = threadIdx.x;
    if (t < 256) sW[t] = W[t];
    if (t < 16)  sB[t] = bias[t];
    __syncthreads();
    int warp = (blockIdx.x * blockDim.x + t) >> 5;
    int lane = t & 31;
    int v = 2 * warp + (lane >> 4);
    if (v >= V_) return;
    int b = lane & 15;
    float dv = g_dinv[v];
    const float4* self = &tin[(size_t)v * 64 + b * 4];
    float4 a0 = self[0], a1 = self[1], a2 = self[2], a3 = self[3];
    int e1 = g_off[v + 1];
    for (int e = g_off[v]; e < e1; e++) {
        int s = g_csr[e];
        const float4* nb = &tin[(size_t)s * 64 + b * 4];
        float4 r0 = nb[0], r1 = nb[1], r2 = nb[2], r3 = nb[3];
        a0.x += r0.x; a0.y += r0.y; a0.z += r0.z; a0.w += r0.w;
        a1.x += r1.x; a1.y += r1.y; a1.z += r1.z; a1.w += r1.w;
        a2.x += r2.x; a2.y += r2.y; a2.z += r2.z; a2.w += r2.w;
        a3.x += r3.x; a3.y += r3.y; a3.z += r3.z; a3.w += r3.w;
    }
    float h[16] = {a0.x, a0.y, a0.z, a0.w, a1.x, a1.y, a1.z, a1.w,
                   a2.x, a2.y, a2.z, a2.w, a3.x, a3.y, a3.z, a3.w};
#pragma unroll
    for (int k = 0; k < 16; k++) {
        float x = sB[k] + dv * h[k];
        h[k] = (x > 0.f) ? x : NEG * x;
    }
    float o[16];
#pragma unroll
    for (int j = 0; j < 16; j++) o[j] = 0.f;
#pragma unroll
    for (int k = 0; k < 16; k++) {
        float hk = h[k];
#pragma unroll
        for (int j = 0; j < 16; j++) o[j] += hk * sW[k * 16 + j];
    }
    float4* dst = &tout[(size_t)v * 64 + b * 4];
    dst[0] = make_float4(o[0] * dv,  o[1] * dv,  o[2] * dv,  o[3] * dv);
    dst[1] = make_float4(o[4] * dv,  o[5] * dv,  o[6] * dv,  o[7] * dv);
    dst[2] = make_float4(o[8] * dv,  o[9] * dv,  o[10] * dv, o[11] * dv);
    dst[3] = make_float4(o[12] * dv, o[13] * dv, o[14] * dv, o[15] * dv);
}

// ---- Fused AGG(layer2) + GEMM3 (16->3): tt3 -> g_tC[v][b] ----

__global__ void k_agg_gemm3(const float* __restrict__ W3, const float* __restrict__ b2) {
    __shared__ float sW[48];
    __shared__ float sB[16];
    int t = threadIdx.x;
    if (t < 48) sW[t] = W3[t];
    if (t < 16) sB[t] = b2[t];
    __syncthreads();
    int warp = (blockIdx.x * blockDim.x + t) >> 5;
    int lane = t & 31;
    int v = 2 * warp + (lane >> 4);
    if (v >= V_) return;
    int b = lane & 15;
    float dv = g_dinv[v];
    const float4* __restrict__ tin = g_tB;
    const float4* self = &tin[(size_t)v * 64 + b * 4];
    float4 a0 = self[0], a1 = self[1], a2 = self[2], a3 = self[3];
    int e1 = g_off[v + 1];
    for (int e = g_off[v]; e < e1; e++) {
        int s = g_csr[e];
        const float4* nb = &tin[(size_t)s * 64 + b * 4];
        float4 r0 = nb[0], r1 = nb[1], r2 = nb[2], r3 = nb[3];
        a0.x += r0.x; a0.y += r0.y; a0.z += r0.z; a0.w += r0.w;
        a1.x += r1.x; a1.y += r1.y; a1.z += r1.z; a1.w += r1.w;
        a2.x += r2.x; a2.y += r2.y; a2.z += r2.z; a2.w += r2.w;
        a3.x += r3.x; a3.y += r3.y; a3.z += r3.z; a3.w += r3.w;
    }
    float h[16] = {a0.x, a0.y, a0.z, a0.w, a1.x, a1.y, a1.z, a1.w,
                   a2.x, a2.y, a2.z, a2.w, a3.x, a3.y, a3.z, a3.w};
#pragma unroll
    for (int k = 0; k < 16; k++) {
        float x = sB[k] + dv * h[k];
        h[k] = (x > 0.f) ? x : NEG * x;
    }
    float o0 = 0.f, o1 = 0.f, o2 = 0.f;
#pragma unroll
    for (int k = 0; k < 16; k++) {
        o0 += h[k] * sW[k * 3 + 0];
        o1 += h[k] * sW[k * 3 + 1];
        o2 += h[k] * sW[k * 3 + 2];
    }
    g_tC[(size_t)v * 16 + b] = make_float4(o0 * dv, o1 * dv, o2 * dv, 0.f);
}

// ---- Final AGG(layer3) + residual: write g_tD and verts region of d_out ----

__global__ void k_final(const float* __restrict__ verts, const float* __restrict__ b3,
                        float* __restrict__ out) {
    __shared__ float sB[3];
    if (threadIdx.x < 3) sB[threadIdx.x] = b3[threadIdx.x];
    __syncthreads();
    int warp = (blockIdx.x * blockDim.x + threadIdx.x) >> 5;
    int lane = threadIdx.x & 31;
    int v = 2 * warp + (lane >> 4);
    if (v >= V_) return;
    int b = lane & 15;
    float dv = g_dinv[v];
    float4 a = g_tC[(size_t)v * 16 + b];
    int e1 = g_off[v + 1];
    for (int e = g_off[v]; e < e1; e++) {
        float4 r = g_tC[(size_t)g_csr[e] * 16 + b];
        a.x += r.x; a.y += r.y; a.z += r.z;
    }
    const float* xp = verts + ((size_t)b * V_ + v) * 3;
    float r0 = xp[0] + sB[0] + dv * a.x;
    float r1 = xp[1] + sB[1] + dv * a.y;
    float r2 = xp[2] + sB[2] + dv * a.z;
    size_t o = ((size_t)b * ROWS + v) * 3;
    out[o + 0] = r0;
    out[o + 1] = r1;
    out[o + 2] = r2;
    g_tD[(size_t)v * 16 + b] = make_float4(r0, r1, r2, 0.f);
}

// ---- Edge midpoints: warp per 2 edges, lane-per-(edge,batch) ----

__global__ void k_mid(const int* __restrict__ edges, float* __restrict__ out) {
    int warp = (blockIdx.x * blockDim.x + threadIdx.x) >> 5;
    int lane = threadIdx.x & 31;
    int e = 2 * warp + (lane >> 4);
    if (e >= E_) return;
    int b = lane & 15;
    int v0 = edges[2 * e], v1 = edges[2 * e + 1];
    float4 p = g_tD[(size_t)v0 * 16 + b];
    float4 q = g_tD[(size_t)v1 * 16 + b];
    size_t o = ((size_t)b * ROWS + V_ + e) * 3;
    out[o + 0] = 0.5f * (p.x + q.x);
    out[o + 1] = 0.5f * (p.y + q.y);
    out[o + 2] = 0.5f * (p.z + q.z);
}

// ---- Faces broadcast (int -> float), vectorized ----

__global__ void k_faces(const int* __restrict__ faces, float* __restrict__ out) {
    int idx = blockIdx.x * blockDim.x + threadIdx.x;
    constexpr int Q = FSUB * 3 / 4;          // 600,000 int4 per batch
    if (idx >= B_ * Q) return;
    int i = idx % Q;
    int4 f = ((const int4*)faces)[i];
    float4 w = make_float4((float)f.x, (float)f.y, (float)f.z, (float)f.w);
    ((float4*)(out + VOUT))[idx] = w;
}

// ---------------------------------------------------------------------------

extern "C" void kernel_launch(void* const* d_in, const int* in_sizes, int n_in,
                              void* d_out, int out_size) {
    const float* verts = (const float*)d_in[0];
    const int*   edges = (const int*)d_in[1];
    const int*   faces = (const int*)d_in[2];
    const float* W1 = (const float*)d_in[3];
    const float* b1 = (const float*)d_in[4];
    const float* W2 = (const float*)d_in[5];
    const float* b2 = (const float*)d_in[6];
    const float* W3 = (const float*)d_in[7];
    const float* b3 = (const float*)d_in[8];
    float* out = (float*)d_out;

    // CSR + dinv build (edge structure identical across batches)
    k_hist <<<(E_ + 255) / 256, 256>>>(edges);
    k_scan1<<<NBLK, SCAN_B>>>();
    k_scan2<<<(V_ + 255) / 256, 256>>>();
    k_fill <<<(E_ + 255) / 256, 256>>>(edges);

    // GCN pipeline: warp-per-2-vertices kernels
    int nwarp_v = (V_ + 1) / 2;                       // 50,000 warps
    int nb_v = (nwarp_v * 32 + 255) / 256;            // 6,250 blocks
    k_l1<<<nb_v, 256>>>(verts, W1);
    k_agg_gemm16<<<nb_v, 256>>>(g_tA, g_tB, W2, b1);  // AGG1 + GEMM2
    k_agg_gemm3 <<<nb_v, 256>>>(W3, b2);              // AGG2 + GEMM3
    k_final     <<<nb_v, 256>>>(verts, b3, out);      // AGG3 + residual

    // Midpoints from compact [v][b] buffer
    int nwarp_e = (E_ + 1) / 2;
    k_mid<<<(nwarp_e * 32 + 255) / 256, 256>>>(edges, out);

    // Faces (independent)
    k_faces<<<(B_ * FSUB * 3 / 4 + 255) / 256, 256>>>(faces, out);
}

// round 3
// speedup vs baseline: 1.4456x; 1.1849x over previous
#include <cuda_runtime.h>

// ---------------------------------------------------------------------------
// SubdivideMeshes: batched GCN (3 layers) + edge-midpoint subdivision.
// B=16, V=100000, E=300000, Fsub=800000, H=16.
// Features in [V][B][H] layout: one 1KB-contiguous gather per (vertex,edge)
// serves all 16 batches. ELL adjacency, indices broadcast via shuffles.
// Output (float32): [B, V+E, 3] new_verts then [B, Fsub, 3] faces.
// Launch order puts k_agg_gemm16 at slot 4 (the ncu-profiled launch).
// ---------------------------------------------------------------------------

constexpr int   B_    = 16;
constexpr int   V_    = 100000;
constexpr int   E_    = 300000;
constexpr int   FSUB  = 800000;
constexpr int   ROWS  = V_ + E_;          // 400,000 rows per batch
constexpr int   VOUT  = B_ * ROWS * 3;    // verts region floats
constexpr float NEG   = 0.01f;
constexpr int   W_ELL = 32;               // max in-degree supported (Poisson(3))

// Scratch (device globals; allocation-free per harness rules)
__device__ float4 g_tA[V_ * 64];     // [v][b][h/4]  102.4 MB
__device__ float4 g_tB[V_ * 64];     // 102.4 MB
__device__ float4 g_tC[V_ * 16];     // [v][b] tt3 (xyz)
__device__ float4 g_tD[V_ * 16];     // [v][b] final positions
__device__ int    g_ell[V_ * W_ELL]; // 12.8 MB
__device__ int    g_deg[V_];         // zero-init; reset by k_final each replay

// ---------------- ELL build (one kernel) ----------------

__global__ void k_ell(const int* __restrict__ edges) {
    int e = blockIdx.x * blockDim.x + threadIdx.x;
    if (e >= E_) return;
    int2 sd = ((const int2*)edges)[e];
    int slot = atomicAdd(&g_deg[sd.y], 1);
    if (slot < W_ELL) g_ell[sd.y * W_ELL + slot] = sd.x;
}

// ---------------- Layer 1: tt1[v][b][:] = (x @ W1) * dinv[v] ----------------
// Warp = 2 vertices; lane l -> (v = 2w + (l>>4), b = l&15).

__global__ void k_l1(const float* __restrict__ verts, const float* __restrict__ W1) {
    __shared__ float sW[48];
    if (threadIdx.x < 48) sW[threadIdx.x] = W1[threadIdx.x];
    __syncthreads();
    int warp = (blockIdx.x * blockDim.x + threadIdx.x) >> 5;
    int lane = threadIdx.x & 31;
    int v = 2 * warp + (lane >> 4);
    if (v >= V_) return;
    int b = lane & 15;
    float dv = rsqrtf((float)(g_deg[v] + 1));
    const float* xp = verts + ((size_t)b * V_ + v) * 3;
    float x0 = xp[0], x1 = xp[1], x2 = xp[2];
    float o[16];
#pragma unroll
    for (int j = 0; j < 16; j++)
        o[j] = (x0 * sW[j] + x1 * sW[16 + j] + x2 * sW[32 + j]) * dv;
    float4* dst = &g_tA[(size_t)v * 64 + b * 4];
    dst[0] = make_float4(o[0],  o[1],  o[2],  o[3]);
    dst[1] = make_float4(o[4],  o[5],  o[6],  o[7]);
    dst[2] = make_float4(o[8],  o[9],  o[10], o[11]);
    dst[3] = make_float4(o[12], o[13], o[14], o[15]);
}

// ---- Fused AGG + GEMM (16->16) ----
// tout = ( leaky(bias + dv*(tt[v] + sum_s tt[s])) @ W ) * dv

__global__ void k_agg_gemm16(const float4* __restrict__ tin, float4* __restrict__ tout,
                             const float* __restrict__ W, const float* __restrict__ bias) {
    __shared__ float sW[256];
    __shared__ float sB[16];
    int t = threadIdx.x;
    if (t < 256) sW[t] = W[t];
    if (t < 16)  sB[t] = bias[t];
    __syncthreads();
    int warp = (blockIdx.x * blockDim.x + t) >> 5;
    int lane = t & 31;
    int v = 2 * warp + (lane >> 4);
    if (v >= V_) return;
    int b = lane & 15;
    int dg = g_deg[v];
    float dv = rsqrtf((float)(dg + 1));
    // preload ELL row into registers (lanes cooperatively hold all 32 slots)
    const int* row = &g_ell[v * W_ELL];
    int idx0 = row[b];
    int idx1 = row[b + 16];
    const float4* self = &tin[(size_t)v * 64 + b * 4];
    float4 a0 = self[0], a1 = self[1], a2 = self[2], a3 = self[3];
    int dgmax = __reduce_max_sync(0xffffffffu, dg);
    for (int i = 0; i < dgmax; i++) {
        int sel = (i < 16) ? idx0 : idx1;
        int s = __shfl_sync(0xffffffffu, sel, i & 15, 16);
        if (i < dg) {
            const float4* nb = &tin[(size_t)s * 64 + b * 4];
            float4 r0 = nb[0], r1 = nb[1], r2 = nb[2], r3 = nb[3];
            a0.x += r0.x; a0.y += r0.y; a0.z += r0.z; a0.w += r0.w;
            a1.x += r1.x; a1.y += r1.y; a1.z += r1.z; a1.w += r1.w;
            a2.x += r2.x; a2.y += r2.y; a2.z += r2.z; a2.w += r2.w;
            a3.x += r3.x; a3.y += r3.y; a3.z += r3.z; a3.w += r3.w;
        }
    }
    float h[16] = {a0.x, a0.y, a0.z, a0.w, a1.x, a1.y, a1.z, a1.w,
                   a2.x, a2.y, a2.z, a2.w, a3.x, a3.y, a3.z, a3.w};
#pragma unroll
    for (int k = 0; k < 16; k++) {
        float x = sB[k] + dv * h[k];
        h[k] = (x > 0.f) ? x : NEG * x;
    }
    float o[16];
#pragma unroll
    for (int j = 0; j < 16; j++) o[j] = 0.f;
#pragma unroll
    for (int k = 0; k < 16; k++) {
        float hk = h[k];
#pragma unroll
        for (int j = 0; j < 16; j++) o[j] += hk * sW[k * 16 + j];
    }
    float4* dst = &tout[(size_t)v * 64 + b * 4];
    dst[0] = make_float4(o[0] * dv,  o[1] * dv,  o[2] * dv,  o[3] * dv);
    dst[1] = make_float4(o[4] * dv,  o[5] * dv,  o[6] * dv,  o[7] * dv);
    dst[2] = make_float4(o[8] * dv,  o[9] * dv,  o[10] * dv, o[11] * dv);
    dst[3] = make_float4(o[12] * dv, o[13] * dv, o[14] * dv, o[15] * dv);
}

// ---- Fused AGG(layer2) + GEMM3 (16->3) -> g_tC[v][b] ----

__global__ void k_agg_gemm3(const float* __restrict__ W3, const float* __restrict__ b2) {
    __shared__ float sW[48];
    __shared__ float sB[16];
    int t = threadIdx.x;
    if (t < 48) sW[t] = W3[t];
    if (t < 16) sB[t] = b2[t];
    __syncthreads();
    int warp = (blockIdx.x * blockDim.x + t) >> 5;
    int lane = t & 31;
    int v = 2 * warp + (lane >> 4);
    if (v >= V_) return;
    int b = lane & 15;
    int dg = g_deg[v];
    float dv = rsqrtf((float)(dg + 1));
    const int* row = &g_ell[v * W_ELL];
    int idx0 = row[b];
    int idx1 = row[b + 16];
    const float4* __restrict__ tin = g_tB;
    const float4* self = &tin[(size_t)v * 64 + b * 4];
    float4 a0 = self[0], a1 = self[1], a2 = self[2], a3 = self[3];
    int dgmax = __reduce_max_sync(0xffffffffu, dg);
    for (int i = 0; i < dgmax; i++) {
        int sel = (i < 16) ? idx0 : idx1;
        int s = __shfl_sync(0xffffffffu, sel, i & 15, 16);
        if (i < dg) {
            const float4* nb = &tin[(size_t)s * 64 + b * 4];
            float4 r0 = nb[0], r1 = nb[1], r2 = nb[2], r3 = nb[3];
            a0.x += r0.x; a0.y += r0.y; a0.z += r0.z; a0.w += r0.w;
            a1.x += r1.x; a1.y += r1.y; a1.z += r1.z; a1.w += r1.w;
            a2.x += r2.x; a2.y += r2.y; a2.z += r2.z; a2.w += r2.w;
            a3.x += r3.x; a3.y += r3.y; a3.z += r3.z; a3.w += r3.w;
        }
    }
    float h[16] = {a0.x, a0.y, a0.z, a0.w, a1.x, a1.y, a1.z, a1.w,
                   a2.x, a2.y, a2.z, a2.w, a3.x, a3.y, a3.z, a3.w};
#pragma unroll
    for (int k = 0; k < 16; k++) {
        float x = sB[k] + dv * h[k];
        h[k] = (x > 0.f) ? x : NEG * x;
    }
    float o0 = 0.f, o1 = 0.f, o2 = 0.f;
#pragma unroll
    for (int k = 0; k < 16; k++) {
        o0 += h[k] * sW[k * 3 + 0];
        o1 += h[k] * sW[k * 3 + 1];
        o2 += h[k] * sW[k * 3 + 2];
    }
    g_tC[(size_t)v * 16 + b] = make_float4(o0 * dv, o1 * dv, o2 * dv, 0.f);
}

// ---- Final AGG(layer3) + residual -> compact g_tD (coalesced) ----
// Also resets g_deg for the next graph replay.

__global__ void k_final(const float* __restrict__ verts, const float* __restrict__ b3) {
    __shared__ float sB[3];
    if (threadIdx.x < 3) sB[threadIdx.x] = b3[threadIdx.x];
    __syncthreads();
    int warp = (blockIdx.x * blockDim.x + threadIdx.x) >> 5;
    int lane = threadIdx.x & 31;
    int v = 2 * warp + (lane >> 4);
    if (v >= V_) return;
    int b = lane & 15;
    int dg = g_deg[v];
    float dv = rsqrtf((float)(dg + 1));
    const int* rowp = &g_ell[v * W_ELL];
    int idx0 = rowp[b];
    int idx1 = rowp[b + 16];
    float4 a = g_tC[(size_t)v * 16 + b];
    int dgmax = __reduce_max_sync(0xffffffffu, dg);
    for (int i = 0; i < dgmax; i++) {
        int sel = (i < 16) ? idx0 : idx1;
        int s = __shfl_sync(0xffffffffu, sel, i & 15, 16);
        if (i < dg) {
            float4 r = g_tC[(size_t)s * 16 + b];
            a.x += r.x; a.y += r.y; a.z += r.z;
        }
    }
    const float* xp = verts + ((size_t)b * V_ + v) * 3;
    float r0 = xp[0] + sB[0] + dv * a.x;
    float r1 = xp[1] + sB[1] + dv * a.y;
    float r2 = xp[2] + sB[2] + dv * a.z;
    g_tD[(size_t)v * 16 + b] = make_float4(r0, r1, r2, 0.f);
    if (b == 0) g_deg[v] = 0;   // replay idempotence
}

// ---- Transpose-out: verts region of d_out, coalesced b-major writes ----

__global__ void k_out(float* __restrict__ out) {
    int idx = blockIdx.x * blockDim.x + threadIdx.x;
    if (idx >= B_ * V_) return;
    int b = idx / V_, v = idx - b * V_;
    float4 p = g_tD[(size_t)v * 16 + b];
    size_t o = ((size_t)b * ROWS + v) * 3;
    out[o + 0] = p.x;
    out[o + 1] = p.y;
    out[o + 2] = p.z;
}

// ---- Edge midpoints: coalesced writes, L2-resident reads ----

__global__ void k_mid(const int* __restrict__ edges, float* __restrict__ out) {
    int idx = blockIdx.x * blockDim.x + threadIdx.x;
    if (idx >= B_ * E_) return;
    int b = idx / E_, e = idx - b * E_;
    int2 sd = ((const int2*)edges)[e];
    float4 p = g_tD[(size_t)sd.x * 16 + b];
    float4 q = g_tD[(size_t)sd.y * 16 + b];
    size_t o = ((size_t)b * ROWS + V_ + e) * 3;
    out[o + 0] = 0.5f * (p.x + q.x);
    out[o + 1] = 0.5f * (p.y + q.y);
    out[o + 2] = 0.5f * (p.z + q.z);
}

// ---- Faces broadcast (int -> float), 2D grid, vectorized ----

__global__ void k_faces(const int* __restrict__ faces, float* __restrict__ out) {
    constexpr int Q = FSUB * 3 / 4;   // 600,000 int4 per batch
    int i = blockIdx.x * blockDim.x + threadIdx.x;
    if (i >= Q) return;
    int b = blockIdx.y;
    int4 f = ((const int4*)faces)[i];
    float4 w = make_float4((float)f.x, (float)f.y, (float)f.z, (float)f.w);
    ((float4*)(out + VOUT))[(size_t)b * Q + i] = w;
}

// ---------------------------------------------------------------------------

extern "C" void kernel_launch(void* const* d_in, const int* in_sizes, int n_in,
                              void* d_out, int out_size) {
    const float* verts = (const float*)d_in[0];
    const int*   edges = (const int*)d_in[1];
    const int*   faces = (const int*)d_in[2];
    const float* W1 = (const float*)d_in[3];
    const float* b1 = (const float*)d_in[4];
    const float* W2 = (const float*)d_in[5];
    const float* b2 = (const float*)d_in[6];
    const float* W3 = (const float*)d_in[7];
    const float* b3 = (const float*)d_in[8];
    float* out = (float*)d_out;

    int nwarp_v = (V_ + 1) / 2;
    int nb_v = (nwarp_v * 32 + 255) / 256;

    // 1: faces (independent; biggest pure-stream write)
    dim3 fgrid((FSUB * 3 / 4 + 255) / 256, B_);
    k_faces<<<fgrid, 256>>>(faces, out);
    // 2: ELL adjacency build
    k_ell<<<(E_ + 255) / 256, 256>>>(edges);
    // 3: layer-1 GEMM
    k_l1<<<nb_v, 256>>>(verts, W1);
    // 4: AGG1 + GEMM2  <-- ncu-profiled slot
    k_agg_gemm16<<<nb_v, 256>>>(g_tA, g_tB, W2, b1);
    // 5: AGG2 + GEMM3
    k_agg_gemm3<<<nb_v, 256>>>(W3, b2);
    // 6: AGG3 + residual -> g_tD
    k_final<<<nb_v, 256>>>(verts, b3);
    // 7: verts region of out (coalesced)
    k_out<<<(B_ * V_ + 255) / 256, 256>>>(out);
    // 8: midpoints (coalesced)
    k_mid<<<(B_ * E_ + 255) / 256, 256>>>(edges, out);
}

// round 7
// speedup vs baseline: 3.6424x; 2.5197x over previous
#include <cuda_runtime.h>
#include <cuda_fp16.h>

// ---------------------------------------------------------------------------
// SubdivideMeshes: batched GCN (3 layers) + edge-midpoint subdivision.
// B=16, V=100000, E=300000, Fsub=800000, H=16.
// Feature layout [v][j][b] (j = feature chunk, b = batch lane) in fp16:
//  - each LDG.128 per half-warp covers 256B contiguous (lane stride 16B)
//  - one 512B block per (vertex, edge) serves all 16 batches
// Output (float32): [B, V+E, 3] new_verts then [B, Fsub, 3] faces.
// k_agg_gemm16 is kept at launch slot 4 (the ncu-profiled slot).
// ---------------------------------------------------------------------------

constexpr int   B_    = 16;
constexpr int   V_    = 100000;
constexpr int   E_    = 300000;
constexpr int   FSUB  = 800000;
constexpr int   ROWS  = V_ + E_;
constexpr int   VOUT  = B_ * ROWS * 3;
constexpr float NEG   = 0.01f;
constexpr int   W_ELL = 32;

// Scratch (device globals; allocation-free per harness rules)
__device__ uint4  g_tA[V_ * 32];     // fp16 [v][j2][b]: v*32 + j2*16 + b (51.2 MB)
__device__ uint4  g_tB[V_ * 32];     // 51.2 MB
__device__ float4 g_tC[V_ * 16];     // [v][b] tt3 xyz (25.6 MB)
__device__ float4 g_tD[V_ * 16];     // [v][b] final positions
__device__ float4 g_tX[V_ * 16];     // [v][b] input positions
__device__ int    g_ell[V_ * W_ELL];
__device__ int    g_deg[V_];         // zero-init; reset by k_final each replay

// unpack 8 halves from a uint4 and accumulate into acc[0..7]
__device__ __forceinline__ void acc8(float* acc, uint4 u) {
    const __half2* h = (const __half2*)&u;
#pragma unroll
    for (int k = 0; k < 4; k++) {
        float2 f = __half22float2(h[k]);
        acc[2 * k]     += f.x;
        acc[2 * k + 1] += f.y;
    }
}

__device__ __forceinline__ uint4 pack8(const float* o) {
    uint4 u;
    __half2* h = (__half2*)&u;
#pragma unroll
    for (int k = 0; k < 4; k++) h[k] = __floats2half2_rn(o[2 * k], o[2 * k + 1]);
    return u;
}

// ---------------- ELL build ----------------

__global__ void k_ell(const int* __restrict__ edges) {
    int e = blockIdx.x * blockDim.x + threadIdx.x;
    if (e >= E_) return;
    int2 sd = ((const int2*)edges)[e];
    int slot = atomicAdd(&g_deg[sd.y], 1);
    if (slot < W_ELL) g_ell[sd.y * W_ELL + slot] = sd.x;
}

// ---------------- Layer 1: tt1 = (x @ W1) * dinv, fp16 pack ----------------
// Warp = 2 vertices; lane l -> (v = 2w + (l>>4), b = l&15).

__global__ void k_l1(const float* __restrict__ verts, const float* __restrict__ W1) {
    __shared__ float sW[48];
    if (threadIdx.x < 48) sW[threadIdx.x] = W1[threadIdx.x];
    __syncthreads();
    int warp = (blockIdx.x * blockDim.x + threadIdx.x) >> 5;
    int lane = threadIdx.x & 31;
    int v = 2 * warp + (lane >> 4);
    if (v >= V_) return;
    int b = lane & 15;
    float dv = rsqrtf((float)(g_deg[v] + 1));
    const float* xp = verts + ((size_t)b * V_ + v) * 3;
    float x0 = xp[0], x1 = xp[1], x2 = xp[2];
    g_tX[(size_t)v * 16 + b] = make_float4(x0, x1, x2, 0.f);
    float o[16];
#pragma unroll
    for (int j = 0; j < 16; j++)
        o[j] = (x0 * sW[j] + x1 * sW[16 + j] + x2 * sW[32 + j]) * dv;
    g_tA[(size_t)v * 32 + b]      = pack8(o);
    g_tA[(size_t)v * 32 + 16 + b] = pack8(o + 8);
}

// ---- Fused AGG + GEMM (16->16), fp16 in/out, fp32 accumulate ----

__global__ void k_agg_gemm16(const uint4* __restrict__ tin, uint4* __restrict__ tout,
                             const float* __restrict__ W, const float* __restrict__ bias) {
    __shared__ float sW[256];
    __shared__ float sB[16];
    int t = threadIdx.x;
    if (t < 256) sW[t] = W[t];
    if (t < 16)  sB[t] = bias[t];
    __syncthreads();
    int warp = (blockIdx.x * blockDim.x + t) >> 5;
    int lane = t & 31;
    int v = 2 * warp + (lane >> 4);
    if (v >= V_) return;
    int b = lane & 15;
    int dg = g_deg[v];
    float dv = rsqrtf((float)(dg + 1));
    const int* row = &g_ell[v * W_ELL];
    int idx0 = row[b];
    int idx1 = row[b + 16];
    float acc[16];
#pragma unroll
    for (int j = 0; j < 16; j++) acc[j] = 0.f;
    acc8(acc,     tin[(size_t)v * 32 + b]);
    acc8(acc + 8, tin[(size_t)v * 32 + 16 + b]);
    int dgmax = __reduce_max_sync(0xffffffffu, dg);
    for (int i = 0; i < dgmax; i += 2) {
        int sel0 = (i < 16) ? idx0 : idx1;
        int s0 = __shfl_sync(0xffffffffu, sel0, i & 15, 16);
        int sel1 = ((i + 1) < 16) ? idx0 : idx1;
        int s1 = __shfl_sync(0xffffffffu, sel1, (i + 1) & 15, 16);
        bool p0 = i < dg, p1 = (i + 1) < dg;
        uint4 u0a = {0,0,0,0}, u0b = {0,0,0,0}, u1a = {0,0,0,0}, u1b = {0,0,0,0};
        if (p0) { u0a = tin[(size_t)s0 * 32 + b]; u0b = tin[(size_t)s0 * 32 + 16 + b]; }
        if (p1) { u1a = tin[(size_t)s1 * 32 + b]; u1b = tin[(size_t)s1 * 32 + 16 + b]; }
        if (p0) { acc8(acc, u0a); acc8(acc + 8, u0b); }
        if (p1) { acc8(acc, u1a); acc8(acc + 8, u1b); }
    }
#pragma unroll
    for (int k = 0; k < 16; k++) {
        float x = sB[k] + dv * acc[k];
        acc[k] = (x > 0.f) ? x : NEG * x;
    }
    float o[16];
#pragma unroll
    for (int j = 0; j < 16; j++) o[j] = 0.f;
#pragma unroll
    for (int k = 0; k < 16; k++) {
        float hk = acc[k];
#pragma unroll
        for (int j = 0; j < 16; j++) o[j] += hk * sW[k * 16 + j];
    }
#pragma unroll
    for (int j = 0; j < 16; j++) o[j] *= dv;
    tout[(size_t)v * 32 + b]      = pack8(o);
    tout[(size_t)v * 32 + 16 + b] = pack8(o + 8);
}

// ---- Fused AGG(layer2) + GEMM3 (16->3) -> g_tC[v][b] ----

__global__ void k_agg_gemm3(const float* __restrict__ W3, const float* __restrict__ b2) {
    __shared__ float sW[48];
    __shared__ float sB[16];
    int t = threadIdx.x;
    if (t < 48) sW[t] = W3[t];
    if (t < 16) sB[t] = b2[t];
    __syncthreads();
    int warp = (blockIdx.x * blockDim.x + t) >> 5;
    int lane = t & 31;
    int v = 2 * warp + (lane >> 4);
    if (v >= V_) return;
    int b = lane & 15;
    int dg = g_deg[v];
    float dv = rsqrtf((float)(dg + 1));
    const int* row = &g_ell[v * W_ELL];
    int idx0 = row[b];
    int idx1 = row[b + 16];
    const uint4* __restrict__ tin = g_tB;
    float acc[16];
#pragma unroll
    for (int j = 0; j < 16; j++) acc[j] = 0.f;
    acc8(acc,     tin[(size_t)v * 32 + b]);
    acc8(acc + 8, tin[(size_t)v * 32 + 16 + b]);
    int dgmax = __reduce_max_sync(0xffffffffu, dg);
    for (int i = 0; i < dgmax; i += 2) {
        int sel0 = (i < 16) ? idx0 : idx1;
        int s0 = __shfl_sync(0xffffffffu, sel0, i & 15, 16);
        int sel1 = ((i + 1) < 16) ? idx0 : idx1;
        int s1 = __shfl_sync(0xffffffffu, sel1, (i + 1) & 15, 16);
        bool p0 = i < dg, p1 = (i + 1) < dg;
        uint4 u0a = {0,0,0,0}, u0b = {0,0,0,0}, u1a = {0,0,0,0}, u1b = {0,0,0,0};
        if (p0) { u0a = tin[(size_t)s0 * 32 + b]; u0b = tin[(size_t)s0 * 32 + 16 + b]; }
        if (p1) { u1a = tin[(size_t)s1 * 32 + b]; u1b = tin[(size_t)s1 * 32 + 16 + b]; }
        if (p0) { acc8(acc, u0a); acc8(acc + 8, u0b); }
        if (p1) { acc8(acc, u1a); acc8(acc + 8, u1b); }
    }
#pragma unroll
    for (int k = 0; k < 16; k++) {
        float x = sB[k] + dv * acc[k];
        acc[k] = (x > 0.f) ? x : NEG * x;
    }
    float o0 = 0.f, o1 = 0.f, o2 = 0.f;
#pragma unroll
    for (int k = 0; k < 16; k++) {
        o0 += acc[k] * sW[k * 3 + 0];
        o1 += acc[k] * sW[k * 3 + 1];
        o2 += acc[k] * sW[k * 3 + 2];
    }
    g_tC[(size_t)v * 16 + b] = make_float4(o0 * dv, o1 * dv, o2 * dv, 0.f);
}

// ---- Final AGG(layer3) + residual -> g_tD; resets g_deg for replay ----

__global__ void k_final(const float* __restrict__ b3) {
    __shared__ float sB[3];
    if (threadIdx.x < 3) sB[threadIdx.x] = b3[threadIdx.x];
    __syncthreads();
    int warp = (blockIdx.x * blockDim.x + threadIdx.x) >> 5;
    int lane = threadIdx.x & 31;
    int v = 2 * warp + (lane >> 4);
    if (v >= V_) return;
    int b = lane & 15;
    int dg = g_deg[v];
    float dv = rsqrtf((float)(dg + 1));
    const int* rowp = &g_ell[v * W_ELL];
    int idx0 = rowp[b];
    int idx1 = rowp[b + 16];
    float4 a = g_tC[(size_t)v * 16 + b];
    int dgmax = __reduce_max_sync(0xffffffffu, dg);
    for (int i = 0; i < dgmax; i += 2) {
        int sel0 = (i < 16) ? idx0 : idx1;
        int s0 = __shfl_sync(0xffffffffu, sel0, i & 15, 16);
        int sel1 = ((i + 1) < 16) ? idx0 : idx1;
        int s1 = __shfl_sync(0xffffffffu, sel1, (i + 1) & 15, 16);
        bool p0 = i < dg, p1 = (i + 1) < dg;
        float4 r0 = {0,0,0,0}, r1 = {0,0,0,0};
        if (p0) r0 = g_tC[(size_t)s0 * 16 + b];
        if (p1) r1 = g_tC[(size_t)s1 * 16 + b];
        if (p0) { a.x += r0.x; a.y += r0.y; a.z += r0.z; }
        if (p1) { a.x += r1.x; a.y += r1.y; a.z += r1.z; }
    }
    float4 x = g_tX[(size_t)v * 16 + b];
    float r0 = x.x + sB[0] + dv * a.x;
    float r1 = x.y + sB[1] + dv * a.y;
    float r2 = x.z + sB[2] + dv * a.z;
    g_tD[(size_t)v * 16 + b] = make_float4(r0, r1, r2, 0.f);
    if (b == 0) g_deg[v] = 0;   // replay idempotence
}

// ---- Transpose-out: verts region, coalesced writes ----

__global__ void k_out(float* __restrict__ out) {
    int idx = blockIdx.x * blockDim.x + threadIdx.x;
    if (idx >= B_ * V_) return;
    int b = idx / V_, v = idx - b * V_;
    float4 p = g_tD[(size_t)v * 16 + b];
    size_t o = ((size_t)b * ROWS + v) * 3;
    out[o + 0] = p.x;
    out[o + 1] = p.y;
    out[o + 2] = p.z;
}

// ---- Edge midpoints: coalesced writes, L2-resident reads ----

__global__ void k_mid(const int* __restrict__ edges, float* __restrict__ out) {
    int idx = blockIdx.x * blockDim.x + threadIdx.x;
    if (idx >= B_ * E_) return;
    int b = idx / E_, e = idx - b * E_;
    int2 sd = ((const int2*)edges)[e];
    float4 p = g_tD[(size_t)sd.x * 16 + b];
    float4 q = g_tD[(size_t)sd.y * 16 + b];
    size_t o = ((size_t)b * ROWS + V_ + e) * 3;
    out[o + 0] = 0.5f * (p.x + q.x);
    out[o + 1] = 0.5f * (p.y + q.y);
    out[o + 2] = 0.5f * (p.z + q.z);
}

// ---- Faces broadcast (int -> float), vectorized ----

__global__ void k_faces(const int* __restrict__ faces, float* __restrict__ out) {
    constexpr int Q = FSUB * 3 / 4;
    int i = blockIdx.x * blockDim.x + threadIdx.x;
    if (i >= Q) return;
    int b = blockIdx.y;
    int4 f = ((const int4*)faces)[i];
    float4 w = make_float4((float)f.x, (float)f.y, (float)f.z, (float)f.w);
    ((float4*)(out + VOUT))[(size_t)b * Q + i] = w;
}

// ---------------------------------------------------------------------------

extern "C" void kernel_launch(void* const* d_in, const int* in_sizes, int n_in,
                              void* d_out, int out_size) {
    const float* verts = (const float*)d_in[0];
    const int*   edges = (const int*)d_in[1];
    const int*   faces = (const int*)d_in[2];
    const float* W1 = (const float*)d_in[3];
    const float* b1 = (const float*)d_in[4];
    const float* W2 = (const float*)d_in[5];
    const float* b2 = (const float*)d_in[6];
    const float* W3 = (const float*)d_in[7];
    const float* b3 = (const float*)d_in[8];
    float* out = (float*)d_out;

    int nwarp_v = (V_ + 1) / 2;
    int nb_v = (nwarp_v * 32 + 255) / 256;

    // 1: faces
    dim3 fgrid((FSUB * 3 / 4 + 255) / 256, B_);
    k_faces<<<fgrid, 256>>>(faces, out);
    // 2: ELL adjacency
    k_ell<<<(E_ + 255) / 256, 256>>>(edges);
    // 3: layer-1 GEMM (also caches positions to g_tX)
    k_l1<<<nb_v, 256>>>(verts, W1);
    // 4: AGG1 + GEMM2  <-- ncu-profiled slot
    k_agg_gemm16<<<nb_v, 256>>>(g_tA, g_tB, W2, b1);
    // 5: AGG2 + GEMM3
    k_agg_gemm3<<<nb_v, 256>>>(W3, b2);
    // 6: AGG3 + residual -> g_tD
    k_final<<<nb_v, 256>>>(b3);
    // 7: verts region of out
    k_out<<<(B_ * V_ + 255) / 256, 256>>>(out);
    // 8: midpoints
    k_mid<<<(B_ * E_ + 255) / 256, 256>>>(edges, out);
}